// round 8
// baseline (speedup 1.0000x reference)
#include <cuda_runtime.h>
#include <cuda_bf16.h>
#include <cstdint>

// MaxUnpooling2D scatter-add.
//   updates: f32 [8,128,128,256] = 33,554,432 elems (134 MB)
//   mask:    i32 same shape, values in [0, 2^24)
//   out:     f32 [8,256,256,256] = 134,217,728 elems (536 MB)
//   flat index = mask[i] + batch * 2^22  (batch offset uses INPUT size)
// Touched range: [0, 46,137,344) words. Tail [46,137,344, N_OUT) never hit.
//
// R7: scatter is SM-side bound by L1tex per-lane replay of divergent REDG
// (~2.1-2.3 cyc/lane; hardware floor ~2.07). Structure for overlap instead:
//   1. zero touched range (must precede atomics)
//   2. ONE kernel, homogeneous blocks: each block (a) streams its slice of the
//      tail zero with __stwt (write-through, no L2 allocate — tail is never
//      re-read and must not evict touched lines), then (b) scatters its 1024
//      float4. Tail DRAM writes drain under the atomic-bound phase.

static constexpr int N_UPD   = 33554432;    // update elems (8 * 2^22)
static constexpr int N_OUT   = 134217728;   // output elems (8 * 2^24)
static constexpr int TOUCHED = 46137344;    // 2^24 + 7*2^22
static constexpr int BATCH_SHIFT = 22;

static constexpr int GRID      = (N_UPD / 4) / 256;            // 32768 blocks
static constexpr int TAIL4     = (N_OUT - TOUCHED) / 4;        // 22,020,096 float4
static constexpr int TAIL_PER_BLOCK = TAIL4 / GRID;            // 672

__global__ void __launch_bounds__(256) zero_touched_kernel(float4* __restrict__ out) {
    int i = blockIdx.x * 256 + threadIdx.x;
    out[i] = make_float4(0.f, 0.f, 0.f, 0.f);
}

__global__ void __launch_bounds__(256) scatter_fused_kernel(
    const float4* __restrict__ upd4,
    const int4*  __restrict__ mask4,
    float* __restrict__ out)
{
    int bid = blockIdx.x;
    int t   = threadIdx.x;
    const float4 z4 = make_float4(0.f, 0.f, 0.f, 0.f);

    // (a) Fire-and-forget tail zero: 672 float4 per block, write-through.
    float4* tail = (float4*)out + (TOUCHED / 4) + bid * TAIL_PER_BLOCK;
#pragma unroll
    for (int j = 0; j < 3; j++) {
        int idx = t + j * 256;
        if (idx < TAIL_PER_BLOCK) __stwt(tail + idx, z4);
    }

    // (b) Scatter: 4 elems per thread (fastest shape from R3).
    int i = bid * 256 + t;                        // float4 index
    int4   m = __ldcs(mask4 + i);
    float4 u = __ldcs(upd4 + i);
    // elem index = 4*i -> batch = i >> 20; base = batch << 22
    int base = (i >> (BATCH_SHIFT - 2)) << BATCH_SHIFT;
    atomicAdd(out + (base + m.x), u.x);
    atomicAdd(out + (base + m.y), u.y);
    atomicAdd(out + (base + m.z), u.z);
    atomicAdd(out + (base + m.w), u.w);
}

extern "C" void kernel_launch(void* const* d_in, const int* in_sizes, int n_in,
                              void* d_out, int out_size) {
    const float* updates = (const float*)d_in[0];
    const int*   mask    = (const int*)d_in[1];
    float* out = (float*)d_out;

    // 1. Zero touched range [0, TOUCHED) — ordering hazard with atomics.
    zero_touched_kernel<<<(TOUCHED / 4) / 256, 256>>>((float4*)out);

    // 2. Fused tail-zero + scatter.
    scatter_fused_kernel<<<GRID, 256>>>(
        (const float4*)updates, (const int4*)mask, out);
}

// round 9
// speedup vs baseline: 1.1451x; 1.1451x over previous
#include <cuda_runtime.h>
#include <cuda_bf16.h>
#include <cstdint>

// MaxUnpooling2D scatter-add.
//   updates: f32 [8,128,128,256] = 33,554,432 elems (134 MB)
//   mask:    i32 same shape, values in [0, 2^24)
//   out:     f32 [8,256,256,256] = 134,217,728 elems (536 MB)
//   flat index = mask[i] + batch * 2^22  (batch offset uses INPUT size)
// Touched range: [0, 46,137,344) words. Tail [46,137,344, N_OUT) never hit.
//
// R8: scatter is bound by L1tex divergent-REDG wavefront replay
// (~2.3 cyc/lane, invariant to L2/MLP/occupancy). Only schedule is winnable:
//   1. zero touched range (hazard, serial, ~29us)
//   2. fused kernel: per block, LDGs first (critical path), atomics, then
//      3 fire-and-forget __stcs tail stores. Tail DRAM writes drain under the
//      atomic-bound phase because every wave carries both roles.
// (R7 failed on __stwt + stores-before-loads; both corrected here.)

static constexpr int N_UPD   = 33554432;    // update elems (8 * 2^22)
static constexpr int N_OUT   = 134217728;   // output elems (8 * 2^24)
static constexpr int TOUCHED = 46137344;    // 2^24 + 7*2^22
static constexpr int BATCH_SHIFT = 22;

static constexpr int GRID  = (N_UPD / 4) / 256;          // 32768 blocks
static constexpr int TAIL4 = (N_OUT - TOUCHED) / 4;      // 22,020,096 float4
static constexpr int TAIL_PER_BLOCK = TAIL4 / GRID;      // 672 (= 2.625/thread)

__global__ void __launch_bounds__(256) zero_touched_kernel(float4* __restrict__ out) {
    int i = blockIdx.x * 256 + threadIdx.x;
    out[i] = make_float4(0.f, 0.f, 0.f, 0.f);
}

__global__ void __launch_bounds__(256) scatter_fused_kernel(
    const float4* __restrict__ upd4,
    const int4*  __restrict__ mask4,
    float* __restrict__ out)
{
    int bid = blockIdx.x;
    int t   = threadIdx.x;

    // (1) Critical path first: issue both wide loads immediately.
    int i = bid * 256 + t;                        // float4 index
    int4   m = mask4[i];
    float4 u = upd4[i];

    // (2) Scatter: 4 divergent REDG lanes per thread (R3's fastest shape).
    // elem index = 4*i -> batch = i >> 20; base = batch << 22
    int base = (i >> (BATCH_SHIFT - 2)) << BATCH_SHIFT;
    atomicAdd(out + (base + m.x), u.x);
    atomicAdd(out + (base + m.y), u.y);
    atomicAdd(out + (base + m.z), u.z);
    atomicAdd(out + (base + m.w), u.w);

    // (3) Fire-and-forget tail zero: 672 float4 per block, evict-first.
    const float4 z4 = make_float4(0.f, 0.f, 0.f, 0.f);
    float4* tail = (float4*)out + (TOUCHED / 4) + bid * TAIL_PER_BLOCK;
#pragma unroll
    for (int j = 0; j < 3; j++) {
        int idx = t + j * 256;
        if (idx < TAIL_PER_BLOCK) __stcs(tail + idx, z4);
    }
}

extern "C" void kernel_launch(void* const* d_in, const int* in_sizes, int n_in,
                              void* d_out, int out_size) {
    const float* updates = (const float*)d_in[0];
    const int*   mask    = (const int*)d_in[1];
    float* out = (float*)d_out;

    // 1. Zero touched range [0, TOUCHED) — must precede all atomics.
    zero_touched_kernel<<<(TOUCHED / 4) / 256, 256>>>((float4*)out);

    // 2. Fused scatter + tail zero.
    scatter_fused_kernel<<<GRID, 256>>>(
        (const float4*)updates, (const int4*)mask, out);
}

// round 11
// speedup vs baseline: 1.2899x; 1.1264x over previous
#include <cuda_runtime.h>
#include <cuda_bf16.h>
#include <cstdint>

// MaxUnpooling2D scatter-add.
//   updates: f32 [8,128,128,256] = 33,554,432 elems (134 MB)
//   mask:    i32 same shape, values in [0, 2^24)
//   out:     f32 [8,256,256,256] = 134,217,728 elems (536 MB)
//   flat index = mask[i] + batch * 2^22  (batch offset uses INPUT size)
// Touched range: [0, 46,137,344) words; tail never hit by atomics.
//
// R9: atomic work (~250-290us of divergent-REDG L1tex wavefronts) is a hard
// floor; in-kernel fusion of zeroing with it loses (R7/R8). Instead use a
// capture-legal fork-join second stream:
//   main: zero_p0 -> pass0 (targets [0,PART)) -> wait side -> pass1
//   side: zero [PART, N_OUT)  (contiguous partition-1 + tail, 445 MB)
// side has NO hazard with pass0 (disjoint ranges) and overlaps its DRAM
// traffic under the atomic-bound pass0.

static constexpr int N_UPD   = 33554432;    // update elems (8 * 2^22)
static constexpr int N_OUT   = 134217728;   // output elems (8 * 2^24)
static constexpr int TOUCHED = 46137344;    // 2^24 + 7*2^22
static constexpr int PART    = TOUCHED / 2; // 23,068,672
static constexpr int BATCH_SHIFT = 22;

static constexpr int SCATTER_BLOCKS = (N_UPD / 4) / 256;   // 32768
static constexpr int P0_BLOCKS   = (PART / 4) / 256;       // 22528
static constexpr int SIDE_BLOCKS = ((N_OUT - PART) / 4) / 256;  // 108544

// Streams/events created once at load time (host-side resources only).
static cudaStream_t g_side = nullptr;
static cudaEvent_t  g_evFork = nullptr, g_evSide = nullptr;
namespace {
struct InitOnce {
    InitOnce() {
        cudaStreamCreateWithFlags(&g_side, cudaStreamNonBlocking);
        cudaEventCreateWithFlags(&g_evFork, cudaEventDisableTiming);
        cudaEventCreateWithFlags(&g_evSide, cudaEventDisableTiming);
    }
};
static InitOnce g_init;
}

__global__ void __launch_bounds__(256) zero_range_kernel(float4* __restrict__ out) {
    int i = blockIdx.x * 256 + threadIdx.x;
    out[i] = make_float4(0.f, 0.f, 0.f, 0.f);
}

// One scatter pass: apply only atomics whose target lies in [lo, hi).
__global__ void __launch_bounds__(256) scatter_pass_kernel(
    const float4* __restrict__ upd4,
    const int4*  __restrict__ mask4,
    float* __restrict__ out,
    int lo, int hi)
{
    int i = blockIdx.x * 256 + threadIdx.x;        // float4 index
    int4   m = __ldcs(mask4 + i);
    float4 u = __ldcs(upd4 + i);
    // elem index = 4*i -> batch = i >> 20; base = batch << 22
    int base = (i >> (BATCH_SHIFT - 2)) << BATCH_SHIFT;

    int ix = base + m.x, iy = base + m.y, iz = base + m.z, iw = base + m.w;
    if (ix >= lo && ix < hi) atomicAdd(out + ix, u.x);
    if (iy >= lo && iy < hi) atomicAdd(out + iy, u.y);
    if (iz >= lo && iz < hi) atomicAdd(out + iz, u.z);
    if (iw >= lo && iw < hi) atomicAdd(out + iw, u.w);
}

extern "C" void kernel_launch(void* const* d_in, const int* in_sizes, int n_in,
                              void* d_out, int out_size) {
    const float* updates = (const float*)d_in[0];
    const int*   mask    = (const int*)d_in[1];
    float* out = (float*)d_out;

    // Fork: side stream zeroes the contiguous range [PART, N_OUT)
    // (partition 1 + never-touched tail) concurrently with pass 0.
    cudaEventRecord(g_evFork, 0);
    cudaStreamWaitEvent(g_side, g_evFork, 0);
    zero_range_kernel<<<SIDE_BLOCKS, 256, 0, g_side>>>(
        (float4*)(out + PART));
    cudaEventRecord(g_evSide, g_side);

    // Main: zero partition 0, then scatter pass 0 (targets [0, PART)).
    zero_range_kernel<<<P0_BLOCKS, 256>>>((float4*)out);
    scatter_pass_kernel<<<SCATTER_BLOCKS, 256>>>(
        (const float4*)updates, (const int4*)mask, out, 0, PART);

    // Join: pass 1 (targets [PART, TOUCHED)) needs side's zeroing done.
    cudaStreamWaitEvent(0, g_evSide, 0);
    scatter_pass_kernel<<<SCATTER_BLOCKS, 256>>>(
        (const float4*)updates, (const int4*)mask, out, PART, TOUCHED);
}